// round 17
// baseline (speedup 1.0000x reference)
#include <cuda_runtime.h>
#include <cuda_fp16.h>
#include <cstdint>

// Problem constants (B=8, N=4096, D=512, K=8192)
#define D_DIM      512
#define NUM_CODES  8192
#define NUM_QUERY  32768

// GEMM tiling: CTA 128x256, 8 warps in 2(M) x 4(N), warp tile 64x64, k-slab 64
#define CTA_M   128
#define CTA_N   256
#define KC      64
#define NTILES  (NUM_CODES / CTA_N)    // 32
#define KSLABS  (D_DIM / KC)           // 8
#define CHUNKS  (NTILES * KSLABS)      // 256
#define THREADS 256
#define STAGES  2
#define NEG_INF (-3.402823466e+38f)

// ---- dynamic smem layout ----
// stage s: A [128x64 f16 swizzled, 16KB] @ s*49152, B [256x64 f16, 32KB] @ +16384
#define STG_BYTES 49152
#define SM_CANDV  (STAGES * STG_BYTES)            // 98304
#define SM_CANDI  (SM_CANDV + 6144)               // 104448
#define SM_MBAR   (SM_CANDI + 6144)               // 110592: full0,full1,free0,free1
#define SMEM_TOTAL (SM_MBAR + 64)                 // 110656 B -> 2 CTAs/SM

// ---- device scratch (no cudaMalloc allowed) ----
__device__ __half g_xh[(size_t)NUM_QUERY * D_DIM];   // 32MB fp16
__device__ __half g_ch[(size_t)NUM_CODES * D_DIM];   //  8MB fp16
__device__ float g_cnorm[NUM_CODES];

// ============================ PTX helpers (sm_80/90-level, PTX-portable) ============
__device__ __forceinline__ uint32_t smem_u32(const void* p) {
    uint32_t a;
    asm("{ .reg .u64 t; cvta.to.shared.u64 t, %1; cvt.u32.u64 %0, t; }" : "=r"(a) : "l"(p));
    return a;
}
#define CP_ASYNC16(dst, src) \
    asm volatile("cp.async.cg.shared.global [%0], [%1], 16;" :: "r"(dst), "l"(src))
#define LDMATRIX_X4(r, addr) \
    asm volatile("ldmatrix.sync.aligned.m8n8.x4.shared.b16 {%0,%1,%2,%3}, [%4];" \
        : "=r"((r)[0]), "=r"((r)[1]), "=r"((r)[2]), "=r"((r)[3]) : "r"(addr))
#define MMA_F16ACC(d, a, b) \
    asm volatile("mma.sync.aligned.m16n8k16.row.col.f16.f16.f16.f16 " \
        "{%0,%1}, {%2,%3,%4,%5}, {%6,%7}, {%0,%1};" \
        : "+r"((d)[0]), "+r"((d)[1]) \
        : "r"((a)[0]), "r"((a)[1]), "r"((a)[2]), "r"((a)[3]), "r"((b)[0]), "r"((b)[1]))

#define MBAR_INIT(addr, cnt) \
    asm volatile("mbarrier.init.shared.b64 [%0], %1;" :: "r"((uint32_t)(addr)), "r"((uint32_t)(cnt)) : "memory")
#define MBAR_ARRIVE(addr) \
    asm volatile("mbarrier.arrive.shared.b64 _, [%0];" :: "r"((uint32_t)(addr)) : "memory")
// thread's prior cp.async ops arrive on mbarrier when complete (.noinc: counts against expected)
#define CPASYNC_MBAR_ARRIVE(addr) \
    asm volatile("cp.async.mbarrier.arrive.noinc.shared.b64 [%0];" :: "r"((uint32_t)(addr)) : "memory")
#define MBAR_WAIT(mbar, par) do {                                                      \
    uint32_t _m = (uint32_t)(mbar); uint32_t _p = (uint32_t)(par); uint32_t _d;        \
    asm volatile("{ .reg .pred p; mbarrier.try_wait.parity.acquire.cta.shared::cta.b64 p, [%1], %2;" \
                 " selp.b32 %0, 1, 0, p; }" : "=r"(_d) : "r"(_m), "r"(_p) : "memory"); \
    if (!_d) {                                                                         \
        asm volatile("{ .reg .pred P1;\n"                                              \
            "WL_%=: mbarrier.try_wait.parity.acquire.cta.shared::cta.b64 P1, [%0], %1, 0x989680;\n" \
            "@P1 bra.uni WD_%=;\n bra.uni WL_%=;\nWD_%=: }"                            \
            :: "r"(_m), "r"(_p) : "memory");                                           \
    } } while (0)

// lexicographic "better score": higher value; tie -> lower index (jnp.argmin first-hit)
__device__ __forceinline__ bool better(float v, int i, float w, int j) {
    return (v > w) || (v == w && i < j);
}

// ============================ small kernels ============================
__global__ void __launch_bounds__(256) convert_kernel(const float* __restrict__ src,
                                                      __half* __restrict__ dst, int n4) {
    int i = blockIdx.x * 256 + threadIdx.x;
    if (i >= n4) return;
    float4 v = reinterpret_cast<const float4*>(src)[i];
    __half2* dp = reinterpret_cast<__half2*>(dst) + 2 * i;
    dp[0] = __floats2half2_rn(v.x, v.y);
    dp[1] = __floats2half2_rn(v.z, v.w);
}

__global__ void __launch_bounds__(128) cnorm_kernel(const float* __restrict__ cb) {
    const int code = blockIdx.x;
    const float4 v = reinterpret_cast<const float4*>(cb + (size_t)code * D_DIM)[threadIdx.x];
    float s = v.x * v.x + v.y * v.y + v.z * v.z + v.w * v.w;
#pragma unroll
    for (int off = 16; off > 0; off >>= 1) s += __shfl_xor_sync(0xffffffffu, s, off);
    __shared__ float ws[4];
    if ((threadIdx.x & 31) == 0) ws[threadIdx.x >> 5] = s;
    __syncthreads();
    if (threadIdx.x == 0) g_cnorm[code] = ws[0] + ws[1] + ws[2] + ws[3];
}

// ============================ main fused GEMM+argtop+rescore kernel ==================
__device__ __forceinline__ void insert3(float* V, int* I, float v, int ix) {
    if (better(v, ix, V[0], I[0])) { V[2]=V[1]; I[2]=I[1]; V[1]=V[0]; I[1]=I[0]; V[0]=v; I[0]=ix; }
    else if (better(v, ix, V[1], I[1])) { V[2]=V[1]; I[2]=I[1]; V[1]=v; I[1]=ix; }
    else if (better(v, ix, V[2], I[2])) { V[2]=v; I[2]=ix; }
}

__global__ void __launch_bounds__(THREADS, 2) vq_main(
    const __half* __restrict__ Xh,
    const __half* __restrict__ Ch,
    const float* __restrict__ X,      // fp32 originals for exact rescore
    const float* __restrict__ CB,
    const float* __restrict__ cnorm,
    float* __restrict__ out)
{
    extern __shared__ char smem[];
    const uint32_t sbase = smem_u32(smem);
    const int tid = threadIdx.x, lane = tid & 31, wid = tid >> 5;
    const int warp_m = wid >> 2, warp_n = wid & 3;      // 2 x 4 warp grid, warp = 64x64
    const int rowBase = blockIdx.x * CTA_M;

    float* cv = reinterpret_cast<float*>(smem + SM_CANDV);
    int*   ci = reinterpret_cast<int*>(smem + SM_CANDI);
    for (int i = tid; i < 4 * 128 * 3; i += THREADS) { cv[i] = NEG_INF; ci[i] = 0; }

    // mbarriers: full[s] count=256 (per-thread cp.async arrivals), free[s] count=8 (lane0/warp)
    const uint32_t mbF0 = sbase + SM_MBAR,      mbF1 = sbase + SM_MBAR + 8;
    const uint32_t mbE0 = sbase + SM_MBAR + 16, mbE1 = sbase + SM_MBAR + 24;
    if (tid == 0) {
        MBAR_INIT(mbF0, 256); MBAR_INIT(mbF1, 256);
        MBAR_INIT(mbE0, 8);   MBAR_INIT(mbE1, 8);
    }
    __syncthreads();

    const uint32_t aGlobBase = (uint32_t)rowBase * D_DIM;

    // issue chunk's A (1024 granules) + B (2048 granules) slab into its stage
    auto issue = [&](int cnt) {
        const uint32_t k0 = (uint32_t)(cnt & 7) * KC;
        const uint32_t offA = aGlobBase + k0;
        const uint32_t offB = (uint32_t)(cnt >> 3) * (CTA_N * D_DIM) + k0;
        const uint32_t sA = sbase + (uint32_t)(cnt & 1) * STG_BYTES;
        const uint32_t sB = sA + 16384;
#pragma unroll
        for (int j = 0; j < 4; j++) {          // A: 128 rows x 8 granules
            const int g = tid + j * THREADS;
            const int r = g >> 3, c = g & 7;
            const uint32_t rel = (uint32_t)(r * D_DIM + c * 8);
            const uint32_t sw  = (uint32_t)(r * 128 + ((c ^ (r & 7)) << 4));
            CP_ASYNC16(sA + sw, Xh + offA + rel);
        }
#pragma unroll
        for (int j = 0; j < 8; j++) {          // B: 256 rows x 8 granules
            const int g = tid + j * THREADS;
            const int r = g >> 3, c = g & 7;
            const uint32_t rel = (uint32_t)(r * D_DIM + c * 8);
            const uint32_t sw  = (uint32_t)(r * 128 + ((c ^ (r & 7)) << 4));
            CP_ASYNC16(sB + sw, Ch + offB + rel);
        }
    };

    // ---- per-warp ldmatrix constants (row&7 == lane&7 for A and B rows) ----
    const uint32_t xorc  = (uint32_t)(lane & 7) << 4;
    const uint32_t halfA = (uint32_t)(lane >> 4) << 4;          // k-half select for A
    const uint32_t halfB = (uint32_t)((lane >> 3) & 1) << 4;    // k-half select for B
    uint32_t aRowB[4], bRowB[4];
#pragma unroll
    for (int mt = 0; mt < 4; mt++)
        aRowB[mt] = (uint32_t)((warp_m * 64 + mt * 16 + (lane & 15)) * 128);
#pragma unroll
    for (int h = 0; h < 4; h++)                                  // 4 n16 groups = 64 cols
        bRowB[h] = (uint32_t)((warp_n * 64 + h * 16 + ((lane >> 4) << 3) + (lane & 7)) * 128) + 16384;

    // f16x2-packed accumulators: acc[mt][nt][r], r0={c0,c1}, r1={c2,c3}
    uint32_t acc[4][8][2];
#pragma unroll
    for (int m = 0; m < 4; m++)
#pragma unroll
        for (int n = 0; n < 8; n++) { acc[m][n][0] = 0u; acc[m][n][1] = 0u; }

    // prologue: produce chunks 0 and 1 (no free-wait for first use of each stage)
    issue(0); CPASYNC_MBAR_ARRIVE(mbF0);
    issue(1); CPASYNC_MBAR_ARRIVE(mbF1);

    for (int cnt = 0; cnt < CHUNKS; cnt++) {
        const uint32_t s   = (uint32_t)(cnt & 1);
        const uint32_t par = (uint32_t)((cnt >> 1) & 1);
        const uint32_t mbF = s ? mbF1 : mbF0;
        const uint32_t mbE = s ? mbE1 : mbE0;

        MBAR_WAIT(mbF, par);   // chunk `cnt` data resident (this warp only — no CTA lockstep)

        const uint32_t sS = sbase + s * STG_BYTES;
#pragma unroll
        for (int kk = 0; kk < 4; kk++) {       // k16 steps: 8 LDSM -> 32 MMA
            uint32_t a[4][4], b[8][2];
            const uint32_t colA = (uint32_t)(kk << 5) + halfA;
            const uint32_t colB = (uint32_t)(kk << 5) + halfB;
#pragma unroll
            for (int mt = 0; mt < 4; mt++)
                LDMATRIX_X4(a[mt], sS + aRowB[mt] + (colA ^ xorc));
#pragma unroll
            for (int h = 0; h < 4; h++) {
                uint32_t r4[4];
                LDMATRIX_X4(r4, sS + bRowB[h] + (colB ^ xorc));
                b[2 * h][0] = r4[0];     b[2 * h][1] = r4[1];
                b[2 * h + 1][0] = r4[2]; b[2 * h + 1][1] = r4[3];
            }
#pragma unroll
            for (int mt = 0; mt < 4; mt++)
#pragma unroll
                for (int nt = 0; nt < 8; nt++)
                    MMA_F16ACC(acc[mt][nt], a[mt], b[nt]);
        }
        // MMA register deps guarantee all LDSM reads of this stage completed.
        __syncwarp();
        if (lane == 0) MBAR_ARRIVE(mbE);       // this warp done with stage s (use cnt>>1)

        // produce chunk cnt+2 into stage s once ALL warps are done with it
        if (cnt + 2 < CHUNKS) {
            MBAR_WAIT(mbE, par);               // free[s] completion #(cnt>>1)
            issue(cnt + 2);
            CPASYNC_MBAR_ARRIVE(mbF);          // completes full[s] for use (cnt>>1)+1
        }

        // ---- per-N-tile fused epilogue (every 8th chunk; touches only regs + cand smem) ----
        if ((cnt & 7) == 7) {
            const int ntile = cnt >> 3;
            const int colq = ntile * CTA_N + warp_n * 64 + (lane & 3) * 2;

#pragma unroll
            for (int mt = 0; mt < 4; mt++) {
#pragma unroll
                for (int half = 0; half < 2; half++) {
                    const int row = warp_m * 64 + mt * 16 + (lane >> 2) + half * 8;
                    float v1 = NEG_INF, v2 = NEG_INF; int i1 = 0, i2 = 0;
#pragma unroll
                    for (int nt = 0; nt < 8; nt++) {
                        const int c0 = colq + nt * 8;
                        const float2 p = __half22float2(
                            *reinterpret_cast<const __half2*>(&acc[mt][nt][half]));
                        const float s0 = fmaf(2.f, p.x, -__ldg(cnorm + c0));
                        const float s1 = fmaf(2.f, p.y, -__ldg(cnorm + c0 + 1));
                        if (better(s0, c0, v1, i1))      { v2 = v1; i2 = i1; v1 = s0; i1 = c0; }
                        else if (better(s0, c0, v2, i2)) { v2 = s0; i2 = c0; }
                        if (better(s1, c0 + 1, v1, i1))      { v2 = v1; i2 = i1; v1 = s1; i1 = c0 + 1; }
                        else if (better(s1, c0 + 1, v2, i2)) { v2 = s1; i2 = c0 + 1; }
                    }
                    // merge top-2 across the 4 lanes of the quad (xor 1, 2)
#pragma unroll
                    for (int off = 1; off <= 2; off <<= 1) {
                        const float u1 = __shfl_xor_sync(0xffffffffu, v1, off);
                        const int   j1 = __shfl_xor_sync(0xffffffffu, i1, off);
                        const float u2 = __shfl_xor_sync(0xffffffffu, v2, off);
                        const int   j2 = __shfl_xor_sync(0xffffffffu, i2, off);
                        if (better(u1, j1, v1, i1))      { v2 = v1; i2 = i1; v1 = u1; i1 = j1; }
                        else if (better(u1, j1, v2, i2)) { v2 = u1; i2 = j1; }
                        if (better(u2, j2, v2, i2)) {
                            if (better(u2, j2, v1, i1)) { v2 = v1; i2 = i1; v1 = u2; i1 = j2; }
                            else                         { v2 = u2; i2 = j2; }
                        }
                    }
                    if ((lane & 3) == 0) {   // quad leader updates (warp_n,row) top-3 list
                        const int base = (warp_n * 128 + row) * 3;
                        insert3(cv + base, ci + base, v1, i1);
                        insert3(cv + base, ci + base, v2, i2);
                    }
                }
            }
#pragma unroll
            for (int m = 0; m < 4; m++)
#pragma unroll
                for (int n = 0; n < 8; n++) { acc[m][n][0] = 0u; acc[m][n][1] = 0u; }
        }
    }

    __syncthreads();   // all cand lists visible before cross-warp merge

    // ---- merge 4 quarters x top-3 -> top-4 candidates per query (registers) ----
    float bv[4] = {NEG_INF, NEG_INF, NEG_INF, NEG_INF};
    int   bi[4] = {0, 0, 0, 0};
    if (tid < CTA_M) {
#pragma unroll
        for (int w = 0; w < 4; w++)
#pragma unroll
            for (int e = 0; e < 3; e++) {
                const float v = cv[(w * 128 + tid) * 3 + e];
                const int  ix = ci[(w * 128 + tid) * 3 + e];
                if (better(v, ix, bv[0], bi[0])) {
                    bv[3]=bv[2]; bi[3]=bi[2]; bv[2]=bv[1]; bi[2]=bi[1];
                    bv[1]=bv[0]; bi[1]=bi[0]; bv[0]=v; bi[0]=ix;
                } else if (better(v, ix, bv[1], bi[1])) {
                    bv[3]=bv[2]; bi[3]=bi[2]; bv[2]=bv[1]; bi[2]=bi[1]; bv[1]=v; bi[1]=ix;
                } else if (better(v, ix, bv[2], bi[2])) {
                    bv[3]=bv[2]; bi[3]=bi[2]; bv[2]=v; bi[2]=ix;
                } else if (better(v, ix, bv[3], bi[3])) {
                    bv[3]=v; bi[3]=ix;
                }
            }
    }
    __syncthreads();                     // cv/ci reads done; safe to reuse region
    int* cand4 = reinterpret_cast<int*>(smem + SM_CANDV);   // 128 x int4
    if (tid < CTA_M) {
#pragma unroll
        for (int k = 0; k < 4; k++) cand4[tid * 4 + k] = bi[k];
    }
    __syncthreads();

    // ---- fused exact fp32 rescore: each warp handles 16 of the CTA's 128 queries ----
    for (int qi = wid; qi < CTA_M; qi += 8) {
        const int q = rowBase + qi;
        int idx[4];
#pragma unroll
        for (int k = 0; k < 4; k++) idx[k] = cand4[qi * 4 + k];
        float d[4] = {0.f, 0.f, 0.f, 0.f};
        const float4* xr = reinterpret_cast<const float4*>(X + (size_t)q * D_DIM);
#pragma unroll
        for (int p = 0; p < 4; p++) {
            const float4 xv = xr[lane + 32 * p];
#pragma unroll
            for (int k = 0; k < 4; k++) {
                const float4 cvv = reinterpret_cast<const float4*>(CB + (size_t)idx[k] * D_DIM)[lane + 32 * p];
                float t;
                t = xv.x - cvv.x; d[k] = fmaf(t, t, d[k]);
                t = xv.y - cvv.y; d[k] = fmaf(t, t, d[k]);
                t = xv.z - cvv.z; d[k] = fmaf(t, t, d[k]);
                t = xv.w - cvv.w; d[k] = fmaf(t, t, d[k]);
            }
        }
#pragma unroll
        for (int k = 0; k < 4; k++)
#pragma unroll
            for (int o = 16; o > 0; o >>= 1) d[k] += __shfl_xor_sync(0xffffffffu, d[k], o);
        if (lane == 0) {
            float bd = d[0]; int bix = idx[0];
#pragma unroll
            for (int k = 1; k < 4; k++)
                if (d[k] < bd || (d[k] == bd && idx[k] < bix)) { bd = d[k]; bix = idx[k]; }
            out[q] = (float)bix;
        }
    }
}

// ============================ entry point ============================
extern "C" void kernel_launch(void* const* d_in, const int* in_sizes, int n_in,
                              void* d_out, int out_size) {
    const float *x, *cb;
    if (in_sizes[0] >= in_sizes[1]) { x = (const float*)d_in[0]; cb = (const float*)d_in[1]; }
    else                            { x = (const float*)d_in[1]; cb = (const float*)d_in[0]; }
    float* out = (float*)d_out;

    void *pxh, *pch, *pcn;
    cudaGetSymbolAddress(&pxh, g_xh);
    cudaGetSymbolAddress(&pch, g_ch);
    cudaGetSymbolAddress(&pcn, g_cnorm);

    cudaFuncSetAttribute(vq_main, cudaFuncAttributeMaxDynamicSharedMemorySize, SMEM_TOTAL);

    convert_kernel<<<(NUM_QUERY * D_DIM / 4 + 255) / 256, 256>>>(x, (__half*)pxh, NUM_QUERY * D_DIM / 4);
    convert_kernel<<<(NUM_CODES * D_DIM / 4 + 255) / 256, 256>>>(cb, (__half*)pch, NUM_CODES * D_DIM / 4);
    cnorm_kernel<<<NUM_CODES, 128>>>(cb);
    vq_main<<<NUM_QUERY / CTA_M, THREADS, SMEM_TOTAL>>>(
        (const __half*)pxh, (const __half*)pch, x, cb, (const float*)pcn, out);
}